// round 6
// baseline (speedup 1.0000x reference)
#include <cuda_runtime.h>
#include <cstdint>

#define VOCAB 32000
#define BOS_ID 1
#define BSZ 8
#define SEQLEN 2048

#define FILL_BLOCKS 64000            // each covers 2048 float4 = 32KB
#define TOTAL_BLOCKS (FILL_BLOCKS + BSZ)

// Scratch: per-row histogram (gmem so fill blocks keep full occupancy).
__device__ int g_counts[BSZ][VOCAB];
// Fill-completion counter and patcher-done counter. Both are returned to 0 by
// block 0's epilogue every launch, so every replay starts from a clean state.
__device__ unsigned g_done = 0;
__device__ unsigned g_patch_done = 0;

__global__ void __launch_bounds__(256) fused_kernel(const int* __restrict__ ids,
                                                    float* __restrict__ out) {
    const int bid = blockIdx.x;
    const int t = threadIdx.x;

    if (bid >= BSZ) {
        // ---------------- FILL PATH: pure -6 stream, no dependencies --------
        float4* out4 = (float4*)out;
        const float4 v = make_float4(-6.0f, -6.0f, -6.0f, -6.0f);
        float4* p = out4 + (long long)(bid - BSZ) * 2048 + t;
        #pragma unroll
        for (int j = 0; j < 8; j++) p[j * 256] = v;

        __threadfence();          // make this thread's stores globally visible
        __syncthreads();          // all threads of the block fenced
        if (t == 0) atomicAdd(&g_done, 1u);
        return;
    }

    // ---------------- HIST + PATCH PATH (blocks 0..7, wave 1) ---------------
    const int b = bid;
    __shared__ int warp_best[8];
    __shared__ int s_pred;

    // 1. Zero this row's histogram (8000 int4 = 128KB).
    int4* c4 = (int4*)g_counts[b];
    for (int i = t; i < VOCAB / 4; i += 256) c4[i] = make_int4(0, 0, 0, 0);
    __threadfence();
    __syncthreads();

    // 2. Accumulate counts with gmem atomics. valid <=> v != 0 && v != 1 <=> v > 1.
    const int* row = ids + b * SEQLEN;
    #pragma unroll
    for (int i = t; i < SEQLEN; i += 256) {
        int vtok = row[i];
        if (vtok > BOS_ID) atomicAdd(&g_counts[b][vtok], 1);
    }
    __threadfence();
    __syncthreads();

    // 3. Argmax scan. Packed key: (count << 15) | (0x7FFF - v).
    //    Higher count wins; equal count -> lower v (argmax tie rule).
    //    count <= 2048 (12 bits), v < 32000 (15 bits) -> packed < 2^27.
    //    __ldcg: bypass L1 (atomics updated L2 only; L1 could hold stale lines).
    int best = 0;
    for (int i = t; i < VOCAB / 4; i += 256) {
        int4 c = __ldcg(&c4[i]);
        int vb = 0x7FFF - 4 * i;
        best = max(best, (c.x << 15) | vb);
        best = max(best, (c.y << 15) | (vb - 1));
        best = max(best, (c.z << 15) | (vb - 2));
        best = max(best, (c.w << 15) | (vb - 3));
    }
    best = __reduce_max_sync(0xFFFFFFFFu, best);
    if ((t & 31) == 0) warp_best[t >> 5] = best;
    __syncthreads();
    if (t < 8) {
        int wb = __reduce_max_sync(0xFFu, warp_best[t]);
        if (t == 0) {
            int cnt = wb >> 15;
            s_pred = (cnt > 0) ? (0x7FFF - (wb & 0x7FFF)) : BOS_ID;
        }
    }
    __syncthreads();
    const int pred = s_pred;

    // 4. Wait for ALL fill blocks to have committed their -6 stores.
    {
        volatile unsigned* gd = &g_done;
        while (*gd < (unsigned)FILL_BLOCKS) __nanosleep(64);
    }
    __threadfence();   // acquire: order patch stores after observed completion

    // 5. Patch +6 at (b, s, pred) for every s. 2048 scattered 4B stores.
    float* base = out + (long long)b * SEQLEN * VOCAB + pred;
    #pragma unroll
    for (int s = t; s < SEQLEN; s += 256) {
        base[(long long)s * VOCAB] = 6.0f;
    }
    __threadfence();
    __syncthreads();
    if (t == 0) atomicAdd(&g_patch_done, 1u);

    // 6. Block 0 resets the counters once every patcher is done, restoring the
    //    clean state for the next (replayed) launch.
    if (b == 0 && t == 0) {
        volatile unsigned* gp = &g_patch_done;
        while (*gp < (unsigned)BSZ) __nanosleep(64);
        g_done = 0;
        g_patch_done = 0;
        __threadfence();
    }
}

// ---------------------------------------------------------------------------
extern "C" void kernel_launch(void* const* d_in, const int* in_sizes, int n_in,
                              void* d_out, int out_size) {
    (void)in_sizes; (void)n_in; (void)out_size;
    const int* ids = (const int*)d_in[0];
    fused_kernel<<<TOTAL_BLOCKS, 256>>>(ids, (float*)d_out);
}